// round 2
// baseline (speedup 1.0000x reference)
#include <cuda_runtime.h>
#include <cstdint>

#define D_SUB 8
#define KC 128
#define SUB 16
#define EMB 128

#define K1_BLOCKS 256
#define K1_THREADS 256
#define K1_WARPS (K1_BLOCKS * K1_THREADS / 32)   // 2048
#define PSTRIDE 2320                              // 8*(256 M +16 w +16 S1) + 16 p/q
#define K2A_BLOCKS 64
#define WARPS_PER_CHUNK (K1_WARPS / K2A_BLOCKS)   // 32

// scratch (no allocation allowed -> __device__ globals)
__device__ float g_part[(size_t)K1_WARPS * PSTRIDE];
__device__ float g_part2[(size_t)K2A_BLOCKS * PSTRIDE];
__device__ float g_A[KC];          // 2*s_k
__device__ float g_G[KC];          // s_k
__device__ float g_B[D_SUB * KC];  // -s_k*(normc_dk + mean_k)

// ---------- packed f32x2 helpers ----------
__device__ __forceinline__ unsigned long long pack2(float lo, float hi) {
    unsigned long long r;
    asm("mov.b64 %0, {%1, %2};" : "=l"(r) : "f"(lo), "f"(hi));
    return r;
}
__device__ __forceinline__ void fma2(unsigned long long& d, unsigned long long a, unsigned long long b) {
    asm("fma.rn.f32x2 %0, %1, %2, %0;" : "+l"(d) : "l"(a), "l"(b));
}
__device__ __forceinline__ float lo2(unsigned long long v) { return __uint_as_float((unsigned)v); }
__device__ __forceinline__ float hi2(unsigned long long v) { return __uint_as_float((unsigned)(v >> 32)); }

// =====================================================================
// Kernel 1: per-warp moment accumulation.
// lane = 4*g + q : g = subspace d (0..7), q = row-quarter of M_d (0..3)
// Each lane accumulates a 4x16 block of M_d = sum x x^T, plus w, S1, p, q.
// =====================================================================
__global__ void k1_moments(const int* __restrict__ ids,
                           const float* __restrict__ wemb, int NI)
{
    int warp = (blockIdx.x * blockDim.x + threadIdx.x) >> 5;
    int lane = threadIdx.x & 31;
    int g = lane >> 2;   // subspace
    int q = lane & 3;    // row quarter

    unsigned long long M2[4][8];
#pragma unroll
    for (int r = 0; r < 4; r++)
#pragma unroll
        for (int p = 0; p < 8; p++) M2[r][p] = 0ull;
    float wv[4] = {0.f, 0.f, 0.f, 0.f};
    float s1[4] = {0.f, 0.f, 0.f, 0.f};
    float pA = 0.f, qA = 0.f;

    for (int n = warp; n < NI; n += K1_WARPS) {
        int id = ids[n];
        const float4* xr = (const float4*)(wemb + (size_t)id * EMB + g * SUB);
        float4 a = xr[0], b = xr[1], c = xr[2], e = xr[3];
        float x[16] = {a.x, a.y, a.z, a.w, b.x, b.y, b.z, b.w,
                       c.x, c.y, c.z, c.w, e.x, e.y, e.z, e.w};
        float nx = 0.f;
#pragma unroll
        for (int i = 0; i < 16; i++) nx = fmaf(x[i], x[i], nx);

        unsigned long long x2[8];
#pragma unroll
        for (int p = 0; p < 8; p++) x2[p] = pack2(x[2 * p], x[2 * p + 1]);

        float4 xq = (q == 0) ? a : ((q == 1) ? b : ((q == 2) ? c : e));
        float rv[4] = {xq.x, xq.y, xq.z, xq.w};
#pragma unroll
        for (int r = 0; r < 4; r++) {
            unsigned long long xd = pack2(rv[r], rv[r]);
#pragma unroll
            for (int p = 0; p < 8; p++) fma2(M2[r][p], xd, x2[p]);
            wv[r] += rv[r] * nx;
            s1[r] += rv[r];
        }
        if (q == 0) { pA += nx; qA += nx * nx; }
    }

    float* base = g_part + (size_t)warp * PSTRIDE + g * 288;
#pragma unroll
    for (int r = 0; r < 4; r++) {
#pragma unroll
        for (int p = 0; p < 8; p++) {
            base[(4 * q + r) * 16 + 2 * p]     = lo2(M2[r][p]);
            base[(4 * q + r) * 16 + 2 * p + 1] = hi2(M2[r][p]);
        }
        base[256 + 4 * q + r] = wv[r];
        base[272 + 4 * q + r] = s1[r];
    }
    if (q == 0) {
        g_part[(size_t)warp * PSTRIDE + 2304 + 2 * g]     = pA;
        g_part[(size_t)warp * PSTRIDE + 2304 + 2 * g + 1] = qA;
    }
}

// =====================================================================
// Kernel 2a: parallel deterministic reduction 2048 -> 64 partials
// =====================================================================
__global__ void k2a_reduce()
{
    int b = blockIdx.x;
    for (int idx = threadIdx.x; idx < PSTRIDE; idx += blockDim.x) {
        float s = 0.f;
        const float* p = g_part + (size_t)b * WARPS_PER_CHUNK * PSTRIDE + idx;
#pragma unroll 4
        for (int w = 0; w < WARPS_PER_CHUNK; w++) s += p[(size_t)w * PSTRIDE];
        g_part2[(size_t)b * PSTRIDE + idx] = s;
    }
}

// =====================================================================
// Kernel 2b: final fp64 reduce + per-k BN coefficients.
//  sum_k  = sum_d [ 2 S1.c - p_d - N*nc ]
//  ssq_k  = sum_d [ 4 c'Mc - 4(w.c + nc*S1.c) + (q_d + 2 nc p_d + N nc^2) ]
// =====================================================================
__global__ void k2b_coeffs(const float* __restrict__ cent, int NI)
{
    __shared__ double mom[PSTRIDE];
    int tid = threadIdx.x;
    for (int idx = tid; idx < PSTRIDE; idx += blockDim.x) {
        double s = 0.0;
        for (int b = 0; b < K2A_BLOCKS; b++)
            s += (double)g_part2[(size_t)b * PSTRIDE + idx];
        mom[idx] = s;
    }
    __syncthreads();

    if (tid < KC) {
        int k = tid;
        double sum = 0.0, ssq = 0.0;
        double ncs[D_SUB];
        double cnt = (double)NI;
        for (int d = 0; d < D_SUB; d++) {
            const float* c = cent + ((size_t)d * KC + k) * SUB;
            double cv[16];
#pragma unroll
            for (int i = 0; i < 16; i++) cv[i] = (double)c[i];
            double nc = 0.0, dotS = 0.0, dotw = 0.0, quad = 0.0;
            const double* Md = mom + d * 288;
#pragma unroll
            for (int i = 0; i < 16; i++) {
                nc   += cv[i] * cv[i];
                dotw += Md[256 + i] * cv[i];
                dotS += Md[272 + i] * cv[i];
                double row = 0.0;
#pragma unroll
                for (int j = 0; j < 16; j++) row += Md[i * 16 + j] * cv[j];
                quad += cv[i] * row;
            }
            ncs[d] = nc;
            double p = mom[2304 + 2 * d], qq = mom[2304 + 2 * d + 1];
            sum += 2.0 * dotS - p - cnt * nc;
            ssq += 4.0 * quad - 4.0 * (dotw + nc * dotS) + (qq + 2.0 * nc * p + cnt * nc * nc);
        }
        double tot  = cnt * (double)D_SUB;
        double mean = sum / tot;
        double var  = ssq / tot - mean * mean;
        double s    = 1.0 / sqrt(var + 0.001);
        g_A[k] = (float)(2.0 * s);
        g_G[k] = (float)s;
        for (int d = 0; d < D_SUB; d++)
            g_B[d * KC + k] = (float)(-s * (ncs[d] + mean));
    }
}

// =====================================================================
// Kernel 3: dots + BN-argmax + centroid gather.
// One warp per (n, d): lane owns k in {lane, lane+32, lane+64, lane+96},
// centroids register-resident as f32x2 pairs, fma.rn.f32x2 mainloop.
// =====================================================================
__global__ void __launch_bounds__(256, 2)
k3_assign(const int* __restrict__ ids,
          const float* __restrict__ wemb,
          const float* __restrict__ cent,
          float* __restrict__ out, int NI)
{
    int lane = threadIdx.x & 31;
    int d = threadIdx.x >> 5;   // warp id = subspace

    unsigned long long c2[4][8];
    float Aj[4], nGj[4], Bj[4];
#pragma unroll
    for (int j = 0; j < 4; j++) {
        int k = lane + 32 * j;
        const float4* cr = (const float4*)(cent + ((size_t)d * KC + k) * SUB);
        float4 a = cr[0], b = cr[1], c = cr[2], e = cr[3];
        c2[j][0] = pack2(a.x, a.y); c2[j][1] = pack2(a.z, a.w);
        c2[j][2] = pack2(b.x, b.y); c2[j][3] = pack2(b.z, b.w);
        c2[j][4] = pack2(c.x, c.y); c2[j][5] = pack2(c.z, c.w);
        c2[j][6] = pack2(e.x, e.y); c2[j][7] = pack2(e.z, e.w);
        Aj[j]  = g_A[k];
        nGj[j] = -g_G[k];
        Bj[j]  = g_B[d * KC + k];
    }

    for (int n = blockIdx.x; n < NI; n += gridDim.x) {
        int id = ids[n];
        const ulonglong2* xp = (const ulonglong2*)(wemb + (size_t)id * EMB + d * SUB);
        ulonglong2 v0 = xp[0], v1 = xp[1], v2 = xp[2], v3 = xp[3];
        unsigned long long x2[8] = {v0.x, v0.y, v1.x, v1.y, v2.x, v2.y, v3.x, v3.y};

        unsigned long long nacc = 0ull;
#pragma unroll
        for (int p = 0; p < 8; p++) fma2(nacc, x2[p], x2[p]);
        float normx = lo2(nacc) + hi2(nacc);

        unsigned long long a0 = 0ull, a1 = 0ull, a2 = 0ull, a3 = 0ull;
#pragma unroll
        for (int p = 0; p < 8; p++) {
            fma2(a0, x2[p], c2[0][p]);
            fma2(a1, x2[p], c2[1][p]);
            fma2(a2, x2[p], c2[2][p]);
            fma2(a3, x2[p], c2[3][p]);
        }

        float d0 = lo2(a0) + hi2(a0);
        float d1 = lo2(a1) + hi2(a1);
        float d2 = lo2(a2) + hi2(a2);
        float d3 = lo2(a3) + hi2(a3);
        float s0 = fmaf(Aj[0], d0, fmaf(nGj[0], normx, Bj[0]));
        float s1 = fmaf(Aj[1], d1, fmaf(nGj[1], normx, Bj[1]));
        float s2 = fmaf(Aj[2], d2, fmaf(nGj[2], normx, Bj[2]));
        float s3 = fmaf(Aj[3], d3, fmaf(nGj[3], normx, Bj[3]));

        // local argmax, first-index tie-break (strict >, ascending k)
        float best = s0; int bk = lane;
        if (s1 > best) { best = s1; bk = lane + 32; }
        if (s2 > best) { best = s2; bk = lane + 64; }
        if (s3 > best) { best = s3; bk = lane + 96; }

        // warp argmax via order-preserving key
        int bits = __float_as_int(best);
        unsigned key = (unsigned)bits ^ (((unsigned)(bits >> 31)) | 0x80000000u);
        unsigned kmax = __reduce_max_sync(0xffffffffu, key);
        unsigned cand = (key == kmax) ? (unsigned)bk : 0xffffu;
        unsigned kb = __reduce_min_sync(0xffffffffu, cand);

        if (lane < 4) {
            const float4* cg = (const float4*)(cent + ((size_t)d * KC + kb) * SUB);
            float4 cw = cg[lane];
            ulonglong2 vv = (lane == 0) ? v0 : ((lane == 1) ? v1 : ((lane == 2) ? v2 : v3));
            float x0 = lo2(vv.x), x1 = hi2(vv.x), x2f = lo2(vv.y), x3 = hi2(vv.y);
            float4 o;
            o.x = __fadd_rn(x0,  __fsub_rn(cw.x, x0));
            o.y = __fadd_rn(x1,  __fsub_rn(cw.y, x1));
            o.z = __fadd_rn(x2f, __fsub_rn(cw.z, x2f));
            o.w = __fadd_rn(x3,  __fsub_rn(cw.w, x3));
            ((float4*)(out + (size_t)n * EMB + d * SUB))[lane] = o;
        }
    }
}

extern "C" void kernel_launch(void* const* d_in, const int* in_sizes, int n_in,
                              void* d_out, int out_size)
{
    const int*   ids  = (const int*)d_in[0];
    const float* wemb = (const float*)d_in[1];
    const float* cent = (const float*)d_in[2];
    float*       out  = (float*)d_out;
    int NI = in_sizes[0];   // 131072

    k1_moments<<<K1_BLOCKS, K1_THREADS>>>(ids, wemb, NI);
    k2a_reduce<<<K2A_BLOCKS, 256>>>();
    k2b_coeffs<<<1, 256>>>(cent, NI);
    k3_assign<<<1024, 256>>>(ids, wemb, cent, out, NI);
}

// round 3
// speedup vs baseline: 1.9838x; 1.9838x over previous
#include <cuda_runtime.h>
#include <cstdint>

#define D_SUB 8
#define KC 128
#define SUB 16
#define EMB 128

#define K1_BLOCKS 256
#define K1_THREADS 256
#define K1_WARPS (K1_BLOCKS * K1_THREADS / 32)   // 2048
#define PSTRIDE 2320                              // 8*(256 M +16 w +16 S1) + 16 p/q
#define K2A_BLOCKS 64
#define WARPS_PER_CHUNK (K1_WARPS / K2A_BLOCKS)   // 32

// scratch (no allocation allowed -> __device__ globals)
__device__ float g_part[(size_t)K1_WARPS * PSTRIDE];
__device__ float g_part2[(size_t)K2A_BLOCKS * PSTRIDE];
__device__ float g_G[KC];          // s_k
__device__ float g_B[D_SUB * KC];  // -s_k*(normc_dk + mean_k)

// ---------- packed f32x2 helpers ----------
__device__ __forceinline__ unsigned long long pack2(float lo, float hi) {
    unsigned long long r;
    asm("mov.b64 %0, {%1, %2};" : "=l"(r) : "f"(lo), "f"(hi));
    return r;
}
__device__ __forceinline__ void fma2(unsigned long long& d, unsigned long long a, unsigned long long b) {
    asm("fma.rn.f32x2 %0, %1, %2, %0;" : "+l"(d) : "l"(a), "l"(b));
}
__device__ __forceinline__ unsigned long long sub2(unsigned long long a, unsigned long long b) {
    unsigned long long r;
    asm("sub.rn.f32x2 %0, %1, %2;" : "=l"(r) : "l"(a), "l"(b));
    return r;
}
__device__ __forceinline__ unsigned long long add2(unsigned long long a, unsigned long long b) {
    unsigned long long r;
    asm("add.rn.f32x2 %0, %1, %2;" : "=l"(r) : "l"(a), "l"(b));
    return r;
}
__device__ __forceinline__ float lo2(unsigned long long v) { return __uint_as_float((unsigned)v); }
__device__ __forceinline__ float hi2(unsigned long long v) { return __uint_as_float((unsigned)(v >> 32)); }

// =====================================================================
// Kernel 1: per-warp moment accumulation.
// lane = 4*g + q : g = subspace d (0..7), q = row-quarter of M_d (0..3)
// Each lane accumulates a 4x16 block of M_d = sum x x^T, plus w, S1, p, q.
// =====================================================================
__global__ void k1_moments(const int* __restrict__ ids,
                           const float* __restrict__ wemb, int NI)
{
    int warp = (blockIdx.x * blockDim.x + threadIdx.x) >> 5;
    int lane = threadIdx.x & 31;
    int g = lane >> 2;   // subspace
    int q = lane & 3;    // row quarter

    unsigned long long M2[4][8];
#pragma unroll
    for (int r = 0; r < 4; r++)
#pragma unroll
        for (int p = 0; p < 8; p++) M2[r][p] = 0ull;
    float wv[4] = {0.f, 0.f, 0.f, 0.f};
    float s1[4] = {0.f, 0.f, 0.f, 0.f};
    float pA = 0.f, qA = 0.f;

#pragma unroll 2
    for (int n = warp; n < NI; n += K1_WARPS) {
        int id = ids[n];
        const float4* xr = (const float4*)(wemb + (size_t)id * EMB + g * SUB);
        float4 a = xr[0], b = xr[1], c = xr[2], e = xr[3];
        float x[16] = {a.x, a.y, a.z, a.w, b.x, b.y, b.z, b.w,
                       c.x, c.y, c.z, c.w, e.x, e.y, e.z, e.w};
        float nx = 0.f;
#pragma unroll
        for (int i = 0; i < 16; i++) nx = fmaf(x[i], x[i], nx);

        unsigned long long x2[8];
#pragma unroll
        for (int p = 0; p < 8; p++) x2[p] = pack2(x[2 * p], x[2 * p + 1]);

        float4 xq = (q == 0) ? a : ((q == 1) ? b : ((q == 2) ? c : e));
        float rv[4] = {xq.x, xq.y, xq.z, xq.w};
#pragma unroll
        for (int r = 0; r < 4; r++) {
            unsigned long long xd = pack2(rv[r], rv[r]);
#pragma unroll
            for (int p = 0; p < 8; p++) fma2(M2[r][p], xd, x2[p]);
            wv[r] += rv[r] * nx;
            s1[r] += rv[r];
        }
        if (q == 0) { pA += nx; qA += nx * nx; }
    }

    float* base = g_part + (size_t)warp * PSTRIDE + g * 288;
#pragma unroll
    for (int r = 0; r < 4; r++) {
#pragma unroll
        for (int p = 0; p < 8; p++) {
            base[(4 * q + r) * 16 + 2 * p]     = lo2(M2[r][p]);
            base[(4 * q + r) * 16 + 2 * p + 1] = hi2(M2[r][p]);
        }
        base[256 + 4 * q + r] = wv[r];
        base[272 + 4 * q + r] = s1[r];
    }
    if (q == 0) {
        g_part[(size_t)warp * PSTRIDE + 2304 + 2 * g]     = pA;
        g_part[(size_t)warp * PSTRIDE + 2304 + 2 * g + 1] = qA;
    }
}

// =====================================================================
// Kernel 2a: parallel deterministic reduction 2048 -> 64 partials
// =====================================================================
__global__ void k2a_reduce()
{
    int b = blockIdx.x;
    for (int idx = threadIdx.x; idx < PSTRIDE; idx += blockDim.x) {
        float s = 0.f;
        const float* p = g_part + (size_t)b * WARPS_PER_CHUNK * PSTRIDE + idx;
#pragma unroll 4
        for (int w = 0; w < WARPS_PER_CHUNK; w++) s += p[(size_t)w * PSTRIDE];
        g_part2[(size_t)b * PSTRIDE + idx] = s;
    }
}

// =====================================================================
// Kernel 2b: final fp64 reduce + per-k BN coefficients.
// =====================================================================
__global__ void k2b_coeffs(const float* __restrict__ cent, int NI)
{
    __shared__ double mom[PSTRIDE];
    int tid = threadIdx.x;
    for (int idx = tid; idx < PSTRIDE; idx += blockDim.x) {
        double s = 0.0;
        for (int b = 0; b < K2A_BLOCKS; b++)
            s += (double)g_part2[(size_t)b * PSTRIDE + idx];
        mom[idx] = s;
    }
    __syncthreads();

    if (tid < KC) {
        int k = tid;
        double sum = 0.0, ssq = 0.0;
        double ncs[D_SUB];
        double cnt = (double)NI;
        for (int d = 0; d < D_SUB; d++) {
            const float* c = cent + ((size_t)d * KC + k) * SUB;
            double cv[16];
#pragma unroll
            for (int i = 0; i < 16; i++) cv[i] = (double)c[i];
            double nc = 0.0, dotS = 0.0, dotw = 0.0, quad = 0.0;
            const double* Md = mom + d * 288;
#pragma unroll
            for (int i = 0; i < 16; i++) {
                nc   += cv[i] * cv[i];
                dotw += Md[256 + i] * cv[i];
                dotS += Md[272 + i] * cv[i];
                double row = 0.0;
#pragma unroll
                for (int j = 0; j < 16; j++) row += Md[i * 16 + j] * cv[j];
                quad += cv[i] * row;
            }
            ncs[d] = nc;
            double p = mom[2304 + 2 * d], qq = mom[2304 + 2 * d + 1];
            sum += 2.0 * dotS - p - cnt * nc;
            ssq += 4.0 * quad - 4.0 * (dotw + nc * dotS) + (qq + 2.0 * nc * p + cnt * nc * nc);
        }
        double tot  = cnt * (double)D_SUB;
        double mean = sum / tot;
        double var  = ssq / tot - mean * mean;
        double s    = 1.0 / sqrt(var + 0.001);
        g_G[k] = (float)s;
        for (int d = 0; d < D_SUB; d++)
            g_B[d * KC + k] = (float)(-s * (ncs[d] + mean));
    }
}

// =====================================================================
// Kernel 3 (redesigned): thread-per-(n,d), centroids in SMEM.
// Block: 256 threads, one subspace d (blockIdx.y). Each thread owns
// TWO tokens. Inner loop over all 128 k: 4 broadcast LDS.128 for the
// centroid + fma2 dot for both tokens + local argmax (first-index via
// strict > ascending k). No warp reductions, huge ILP.
// score_k = s_k * (2*dot - ||x||^2) + B_dk ,  B_dk = -s_k*(||c||^2 + mean)
// =====================================================================
__global__ void __launch_bounds__(256, 2)
k3_assign(const int* __restrict__ ids,
          const float* __restrict__ wemb,
          const float* __restrict__ cent,
          float* __restrict__ out, int NI)
{
    __shared__ float cs[KC][20];   // [k]: c[16], s, B, pad2  (80B rows, 16B aligned)

    int tid = threadIdx.x;
    int d = blockIdx.y;

    for (int i = tid; i < KC * SUB; i += 256) {
        int k = i >> 4, j = i & 15;
        cs[k][j] = cent[((size_t)(d * KC + k)) * SUB + j];
    }
    if (tid < KC) {
        cs[tid][16] = g_G[tid];
        cs[tid][17] = g_B[d * KC + tid];
    }
    __syncthreads();

    int base = blockIdx.x * 512 + tid;
    int n[2] = {base, base + 256};

    unsigned long long X[2][8];
    float nx[2];
    float best[2];
    int bk[2];
    bool valid[2];

#pragma unroll
    for (int t = 0; t < 2; t++) {
        valid[t] = (n[t] < NI);
        int id = valid[t] ? ids[n[t]] : 0;
        const ulonglong2* xp = (const ulonglong2*)(wemb + (size_t)id * EMB + d * SUB);
        ulonglong2 v0 = xp[0], v1 = xp[1], v2 = xp[2], v3 = xp[3];
        X[t][0] = v0.x; X[t][1] = v0.y; X[t][2] = v1.x; X[t][3] = v1.y;
        X[t][4] = v2.x; X[t][5] = v2.y; X[t][6] = v3.x; X[t][7] = v3.y;
        unsigned long long nacc = 0ull;
#pragma unroll
        for (int p = 0; p < 8; p++) fma2(nacc, X[t][p], X[t][p]);
        nx[t] = lo2(nacc) + hi2(nacc);
        best[t] = -3.4e38f;
        bk[t] = 0;
    }

#pragma unroll 2
    for (int k = 0; k < KC; k++) {
        const ulonglong2* cp = (const ulonglong2*)&cs[k][0];
        ulonglong2 c0 = cp[0], c1 = cp[1], c2v = cp[2], c3 = cp[3];
        unsigned long long C[8] = {c0.x, c0.y, c1.x, c1.y, c2v.x, c2v.y, c3.x, c3.y};
        float2 sb = *(const float2*)&cs[k][16];
#pragma unroll
        for (int t = 0; t < 2; t++) {
            unsigned long long acc = 0ull;
#pragma unroll
            for (int p = 0; p < 8; p++) fma2(acc, X[t][p], C[p]);
            float dot = lo2(acc) + hi2(acc);
            float sc = fmaf(sb.x, fmaf(dot, 2.0f, -nx[t]), sb.y);
            if (sc > best[t]) { best[t] = sc; bk[t] = k; }
        }
    }

#pragma unroll
    for (int t = 0; t < 2; t++) {
        if (!valid[t]) continue;
        const ulonglong2* cp = (const ulonglong2*)&cs[bk[t]][0];
        ulonglong2 c0 = cp[0], c1 = cp[1], c2v = cp[2], c3 = cp[3];
        unsigned long long C[8] = {c0.x, c0.y, c1.x, c1.y, c2v.x, c2v.y, c3.x, c3.y};
        unsigned long long O[8];
#pragma unroll
        for (int p = 0; p < 8; p++) O[p] = add2(X[t][p], sub2(C[p], X[t][p]));
        ulonglong2* op = (ulonglong2*)(out + (size_t)n[t] * EMB + d * SUB);
        op[0] = make_ulonglong2(O[0], O[1]);
        op[1] = make_ulonglong2(O[2], O[3]);
        op[2] = make_ulonglong2(O[4], O[5]);
        op[3] = make_ulonglong2(O[6], O[7]);
    }
}

extern "C" void kernel_launch(void* const* d_in, const int* in_sizes, int n_in,
                              void* d_out, int out_size)
{
    const int*   ids  = (const int*)d_in[0];
    const float* wemb = (const float*)d_in[1];
    const float* cent = (const float*)d_in[2];
    float*       out  = (float*)d_out;
    int NI = in_sizes[0];   // 131072

    k1_moments<<<K1_BLOCKS, K1_THREADS>>>(ids, wemb, NI);
    k2a_reduce<<<K2A_BLOCKS, 256>>>();
    k2b_coeffs<<<1, 256>>>(cent, NI);

    dim3 g3((NI + 511) / 512, D_SUB);
    k3_assign<<<g3, 256>>>(ids, wemb, cent, out, NI);
}